// round 13
// baseline (speedup 1.0000x reference)
#include <cuda_runtime.h>
#include <math.h>

#define B 4
#define N 8192
#define M 8192
#define EPS 1e-8f
#define TSR 128   // source rows per CTA
#define TSC 256   // target cols per tile
#define NT  2     // col tiles swept per CTA
#define CGROUPS (M / (TSC * NT))   // 16 col groups
#define RTILES (N / TSR)           // 64

typedef unsigned long long u64;

__device__ float g_rowpart[B * CGROUPS * N];   // [b][colGroup][row]
__device__ float g_colpart[B * RTILES * M];    // [b][rowTile][col]
__device__ float g_bsum[256];

// ---------------- packed f32x2 helpers ----------------
__device__ __forceinline__ u64 pk2(float a, float b) {
    u64 r;
    asm("mov.b64 %0, {%1, %2};" : "=l"(r) : "f"(a), "f"(b));
    return r;
}
__device__ __forceinline__ u64 add2(u64 a, u64 b) {
    u64 r;
    asm("add.rn.f32x2 %0, %1, %2;" : "=l"(r) : "l"(a), "l"(b));
    return r;
}
__device__ __forceinline__ u64 fma2(u64 a, u64 b, u64 c) {
    u64 r;
    asm("fma.rn.f32x2 %0, %1, %2, %3;" : "=l"(r) : "l"(a), "l"(b), "l"(c));
    return r;
}
__device__ __forceinline__ float2 u2f(u64 v) {
    float2 f;
    asm("mov.b64 {%0, %1}, %2;" : "=f"(f.x), "=f"(f.y) : "l"(v));
    return f;
}

// ---------------- fused sweep kernel ----------------
// CTA: 128 source rows x (2 tiles of 256 target cols). 256 threads (16 tyi x 16 txi).
// Thread tile: 8 rows (4 vertical f32x2 pairs, register-resident: 16 u64 = 32 regs)
// x 16 cols (c-blocks col = c*16 + txi, conflict-free LDS.64).
// Low register footprint -> 3 CTAs/SM (24 warps) for latency hiding.
__global__ __launch_bounds__(256, 3) void tile_kernel(const float* __restrict__ source,
                                                      const float* __restrict__ target) {
    __shared__ __align__(16) float s_x[TSR], s_y[TSR], s_z[TSR], s_n[TSR];   // scalar source
    __shared__ __align__(16) u64 td_x[TSC], td_y[TSC], td_z[TSC], td_n[TSC]; // dup (-2t), (nt)
    __shared__ float red[TSC * 17];

    const int tid = threadIdx.x;
    const int b   = blockIdx.z;
    const int row0 = blockIdx.y * TSR;
    const int g    = blockIdx.x;
    const int colg0 = g * (TSC * NT);

    // Stage source (scalar): one row per thread (threads 0..127)
    if (tid < TSR) {
        const float* sp = source + ((long)b * N + row0 + tid) * 3;
        float vx = sp[0], vy = sp[1], vz = sp[2];
        s_x[tid] = vx; s_y[tid] = vy; s_z[tid] = vz;
        s_n[tid] = vx * vx + vy * vy + vz * vz;
    }
    // Stage first target tile: duplicated pairs (one col per thread)
    {
        const float* tp = target + ((long)b * M + colg0 + tid) * 3;
        float vx = tp[0], vy = tp[1], vz = tp[2];
        td_x[tid] = pk2(-2.0f * vx, -2.0f * vx);
        td_y[tid] = pk2(-2.0f * vy, -2.0f * vy);
        td_z[tid] = pk2(-2.0f * vz, -2.0f * vz);
        float n = vx * vx + vy * vy + vz * vz;
        td_n[tid] = pk2(n, n);
    }
    __syncthreads();

    const int txi = tid & 15;
    const int tyi = tid >> 4;
    const int r0 = tyi * 8;   // this thread's 8 rows (4 pairs)

    // Load source row-pairs into registers ONCE (16 u64 = 32 regs)
    u64 px[4], py[4], pz[4], pn[4];
#pragma unroll
    for (int a = 0; a < 4; a++) {
        px[a] = *reinterpret_cast<const u64*>(&s_x[r0 + 2 * a]);
        py[a] = *reinterpret_cast<const u64*>(&s_y[r0 + 2 * a]);
        pz[a] = *reinterpret_cast<const u64*>(&s_z[r0 + 2 * a]);
        pn[a] = *reinterpret_cast<const u64*>(&s_n[r0 + 2 * a]);
    }

    const float BIGF = 3.4e38f;
    float rmin[8];
#pragma unroll
    for (int i = 0; i < 8; i++) rmin[i] = BIGF;

    float nx = 0.f, ny = 0.f, nz = 0.f;  // next-tile prefetch

    for (int ct = 0; ct < NT; ct++) {
        if (ct + 1 < NT) {
            const float* tp = target + ((long)b * M + colg0 + (ct + 1) * TSC + tid) * 3;
            nx = tp[0]; ny = tp[1]; nz = tp[2];
        }

#pragma unroll
        for (int c = 0; c < 16; c++) {
            const int col = c * 16 + txi;   // unit stride across lanes: conflict-free
            u64 tx = td_x[col], ty = td_y[col], tz = td_z[col], tn = td_n[col];
            float cc0 = BIGF, cc1 = BIGF;
#pragma unroll
            for (int a = 0; a < 4; a++) {
                u64 q = fma2(px[a], tx, add2(pn[a], tn));
                q = fma2(py[a], ty, q);
                q = fma2(pz[a], tz, q);       // q = (d^2 row 2a, d^2 row 2a+1)
                float2 f = u2f(q);
                rmin[2 * a]     = fminf(rmin[2 * a], f.x);
                rmin[2 * a + 1] = fminf(rmin[2 * a + 1], f.y);
                cc0 = fminf(cc0, f.x);
                cc1 = fminf(cc1, f.y);
            }
            red[col * 17 + tyi] = fminf(cc0, cc1);
        }
        __syncthreads();
        // col-min reduction across tyi (16 values per col; one col per thread)
        {
            float m = red[tid * 17];
#pragma unroll
            for (int k = 1; k < 16; k++) m = fminf(m, red[tid * 17 + k]);
            g_colpart[((long)b * RTILES + blockIdx.y) * M + colg0 + ct * TSC + tid] = m;
        }
        __syncthreads();

        // Commit prefetched target tile
        if (ct + 1 < NT) {
            td_x[tid] = pk2(-2.0f * nx, -2.0f * nx);
            td_y[tid] = pk2(-2.0f * ny, -2.0f * ny);
            td_z[tid] = pk2(-2.0f * nz, -2.0f * nz);
            float n = nx * nx + ny * ny + nz * nz;
            td_n[tid] = pk2(n, n);
            __syncthreads();
        }
    }

    // ---- row-min reduction (across txi), once per CTA ----
#pragma unroll
    for (int i = 0; i < 8; i++) red[(r0 + i) * 17 + txi] = rmin[i];
    __syncthreads();
    if (tid < TSR) {
        float m = red[tid * 17];
#pragma unroll
        for (int k = 1; k < 16; k++) m = fminf(m, red[tid * 17 + k]);
        g_rowpart[((long)b * CGROUPS + g) * N + row0 + tid] = m;
    }
}

// ---------------- finalize pass 1: reduce partials, block sums ----------------
__global__ void finalize1_kernel(const float* __restrict__ weights) {
    __shared__ float sred[256];
    int tid = blockIdx.x * blockDim.x + threadIdx.x;
    float v;
    if (tid < B * N) {
        int b = tid >> 13, row = tid & 8191;
        const float* p = &g_rowpart[((long)b * CGROUPS) * N + row];
        float m = p[0];
#pragma unroll 8
        for (int ct = 1; ct < CGROUPS; ct++) m = fminf(m, p[(long)ct * N]);
        v = sqrtf(m + EPS) * weights[tid] * (1.0f / (B * N));
    } else {
        int t = tid - B * N;
        int b = t >> 13, col = t & 8191;
        const float* p = &g_colpart[((long)b * RTILES) * M + col];
        float m = p[0];
#pragma unroll 8
        for (int rt = 1; rt < RTILES; rt++) m = fminf(m, p[(long)rt * M]);
        v = sqrtf(m + EPS) * (1.0f / (B * M));
    }
    sred[threadIdx.x] = v;
    __syncthreads();
    for (int s = 128; s > 0; s >>= 1) {
        if (threadIdx.x < s) sred[threadIdx.x] += sred[threadIdx.x + s];
        __syncthreads();
    }
    if (threadIdx.x == 0) g_bsum[blockIdx.x] = sred[0];
}

// ---------------- finalize pass 2: single block, plain store ----------------
__global__ void finalize2_kernel(float* __restrict__ out) {
    __shared__ float sred[256];
    sred[threadIdx.x] = g_bsum[threadIdx.x];
    __syncthreads();
    for (int s = 128; s > 0; s >>= 1) {
        if (threadIdx.x < s) sred[threadIdx.x] += sred[threadIdx.x + s];
        __syncthreads();
    }
    if (threadIdx.x == 0) out[0] = sred[0];
}

extern "C" void kernel_launch(void* const* d_in, const int* in_sizes, int n_in,
                              void* d_out, int out_size) {
    const float* source  = (const float*)d_in[0];
    const float* target  = (const float*)d_in[1];
    const float* weights = (const float*)d_in[2];
    float* out = (float*)d_out;

    dim3 grid(CGROUPS, RTILES, B);
    tile_kernel<<<grid, 256>>>(source, target);

    finalize1_kernel<<<(B * N + B * M) / 256, 256>>>(weights);
    finalize2_kernel<<<1, 256>>>(out);
}

// round 14
// speedup vs baseline: 1.0189x; 1.0189x over previous
#include <cuda_runtime.h>
#include <math.h>

#define B 4
#define N 8192
#define M 8192
#define EPS 1e-8f
#define TSR 256   // source rows per CTA
#define TSC 256   // target cols per tile
#define NT  4     // col tiles swept per CTA
#define CGROUPS (M / (TSC * NT))   // 8 col groups
#define RTILES (N / TSR)           // 32

typedef unsigned long long u64;

__device__ float g_rowpart[B * CGROUPS * N];   // [b][colGroup][row]
__device__ float g_colpart[B * RTILES * M];    // [b][rowTile][col]
__device__ float g_bsum[256];

// ---------------- packed f32x2 helpers ----------------
__device__ __forceinline__ u64 pk2(float a, float b) {
    u64 r;
    asm("mov.b64 %0, {%1, %2};" : "=l"(r) : "f"(a), "f"(b));
    return r;
}
__device__ __forceinline__ u64 add2(u64 a, u64 b) {
    u64 r;
    asm("add.rn.f32x2 %0, %1, %2;" : "=l"(r) : "l"(a), "l"(b));
    return r;
}
__device__ __forceinline__ u64 fma2(u64 a, u64 b, u64 c) {
    u64 r;
    asm("fma.rn.f32x2 %0, %1, %2, %3;" : "=l"(r) : "l"(a), "l"(b), "l"(c));
    return r;
}
__device__ __forceinline__ float2 u2f(u64 v) {
    float2 f;
    asm("mov.b64 {%0, %1}, %2;" : "=f"(f.x), "=f"(f.y) : "l"(v));
    return f;
}

// ---------------- fused sweep kernel ----------------
// CTA: 256 source rows x (4 tiles of 256 target cols). 256 threads (16 tyi x 16 txi).
// Vertical packing: each f32x2 pair = TWO SOURCE ROWS; target duplicated.
// Source (8 pairs x 4 coords = 32 u64) register-resident for the whole CTA.
// Column mapping col = c*16 + txi -> conflict-free LDS.64.
// Fat tiles (256 cols): all 256 threads participate in the col reduction,
// and only 2 barriers per tile x 4 tiles.
__global__ __launch_bounds__(256, 2) void tile_kernel(const float* __restrict__ source,
                                                      const float* __restrict__ target) {
    __shared__ __align__(16) float s_x[TSR], s_y[TSR], s_z[TSR], s_n[TSR];   // scalar source
    __shared__ __align__(16) u64 td_x[TSC], td_y[TSC], td_z[TSC], td_n[TSC]; // dup (-2t), (nt)
    __shared__ float red[TSC * 17];

    const int tid = threadIdx.x;
    const int b   = blockIdx.z;
    const int row0 = blockIdx.y * TSR;
    const int g    = blockIdx.x;
    const int colg0 = g * (TSC * NT);

    // Stage source (scalar): one row per thread
    {
        const float* sp = source + ((long)b * N + row0 + tid) * 3;
        float vx = sp[0], vy = sp[1], vz = sp[2];
        s_x[tid] = vx; s_y[tid] = vy; s_z[tid] = vz;
        s_n[tid] = vx * vx + vy * vy + vz * vz;
    }
    // Stage first target tile: duplicated pairs (one col per thread)
    {
        const float* tp = target + ((long)b * M + colg0 + tid) * 3;
        float vx = tp[0], vy = tp[1], vz = tp[2];
        td_x[tid] = pk2(-2.0f * vx, -2.0f * vx);
        td_y[tid] = pk2(-2.0f * vy, -2.0f * vy);
        td_z[tid] = pk2(-2.0f * vz, -2.0f * vz);
        float n = vx * vx + vy * vy + vz * vz;
        td_n[tid] = pk2(n, n);
    }
    __syncthreads();

    const int txi = tid & 15;
    const int tyi = tid >> 4;
    const int r0 = tyi * 16;  // this thread's 16 rows

    // Load source row-pairs into registers ONCE (LDS.64 of adjacent scalars)
    u64 px[8], py[8], pz[8], pn[8];
#pragma unroll
    for (int a = 0; a < 8; a++) {
        px[a] = *reinterpret_cast<const u64*>(&s_x[r0 + 2 * a]);
        py[a] = *reinterpret_cast<const u64*>(&s_y[r0 + 2 * a]);
        pz[a] = *reinterpret_cast<const u64*>(&s_z[r0 + 2 * a]);
        pn[a] = *reinterpret_cast<const u64*>(&s_n[r0 + 2 * a]);
    }

    const float BIGF = 3.4e38f;
    float rmin[16];
#pragma unroll
    for (int i = 0; i < 16; i++) rmin[i] = BIGF;

    float nx = 0.f, ny = 0.f, nz = 0.f;  // next-tile prefetch

    for (int ct = 0; ct < NT; ct++) {
        if (ct + 1 < NT) {
            const float* tp = target + ((long)b * M + colg0 + (ct + 1) * TSC + tid) * 3;
            nx = tp[0]; ny = tp[1]; nz = tp[2];
        }

#pragma unroll
        for (int c = 0; c < 16; c++) {
            const int col = c * 16 + txi;   // unit stride across lanes: conflict-free
            u64 tx = td_x[col], ty = td_y[col], tz = td_z[col], tn = td_n[col];
            float cc0 = BIGF, cc1 = BIGF;  // two independent col-min chains
#pragma unroll
            for (int a = 0; a < 8; a++) {
                u64 q = fma2(px[a], tx, add2(pn[a], tn));
                q = fma2(py[a], ty, q);
                q = fma2(pz[a], tz, q);       // q = (d^2 row 2a, d^2 row 2a+1)
                float2 f = u2f(q);
                rmin[2 * a]     = fminf(rmin[2 * a], f.x);
                rmin[2 * a + 1] = fminf(rmin[2 * a + 1], f.y);
                cc0 = fminf(cc0, f.x);
                cc1 = fminf(cc1, f.y);
            }
            red[col * 17 + tyi] = fminf(cc0, cc1);
        }
        __syncthreads();
        // col-min reduction across tyi: one col per thread, all 256 threads busy
        {
            float m = red[tid * 17];
#pragma unroll
            for (int k = 1; k < 16; k++) m = fminf(m, red[tid * 17 + k]);
            g_colpart[((long)b * RTILES + blockIdx.y) * M + colg0 + ct * TSC + tid] = m;
        }
        __syncthreads();

        // Commit prefetched target tile
        if (ct + 1 < NT) {
            td_x[tid] = pk2(-2.0f * nx, -2.0f * nx);
            td_y[tid] = pk2(-2.0f * ny, -2.0f * ny);
            td_z[tid] = pk2(-2.0f * nz, -2.0f * nz);
            float n = nx * nx + ny * ny + nz * nz;
            td_n[tid] = pk2(n, n);
            __syncthreads();
        }
    }

    // ---- row-min reduction (across txi), once per CTA ----
#pragma unroll
    for (int i = 0; i < 16; i++) red[(r0 + i) * 17 + txi] = rmin[i];
    __syncthreads();
    {
        float m = red[tid * 17];
#pragma unroll
        for (int k = 1; k < 16; k++) m = fminf(m, red[tid * 17 + k]);
        g_rowpart[((long)b * CGROUPS + g) * N + row0 + tid] = m;
    }
}

// ---------------- finalize pass 1: reduce partials, block sums ----------------
__global__ void finalize1_kernel(const float* __restrict__ weights) {
    __shared__ float sred[256];
    int tid = blockIdx.x * blockDim.x + threadIdx.x;
    float v;
    if (tid < B * N) {
        int b = tid >> 13, row = tid & 8191;
        const float* p = &g_rowpart[((long)b * CGROUPS) * N + row];
        float m = p[0];
#pragma unroll 8
        for (int ct = 1; ct < CGROUPS; ct++) m = fminf(m, p[(long)ct * N]);
        v = sqrtf(m + EPS) * weights[tid] * (1.0f / (B * N));
    } else {
        int t = tid - B * N;
        int b = t >> 13, col = t & 8191;
        const float* p = &g_colpart[((long)b * RTILES) * M + col];
        float m = p[0];
#pragma unroll 8
        for (int rt = 1; rt < RTILES; rt++) m = fminf(m, p[(long)rt * M]);
        v = sqrtf(m + EPS) * (1.0f / (B * M));
    }
    sred[threadIdx.x] = v;
    __syncthreads();
    for (int s = 128; s > 0; s >>= 1) {
        if (threadIdx.x < s) sred[threadIdx.x] += sred[threadIdx.x + s];
        __syncthreads();
    }
    if (threadIdx.x == 0) g_bsum[blockIdx.x] = sred[0];
}

// ---------------- finalize pass 2: single block, plain store ----------------
__global__ void finalize2_kernel(float* __restrict__ out) {
    __shared__ float sred[256];
    sred[threadIdx.x] = g_bsum[threadIdx.x];
    __syncthreads();
    for (int s = 128; s > 0; s >>= 1) {
        if (threadIdx.x < s) sred[threadIdx.x] += sred[threadIdx.x + s];
        __syncthreads();
    }
    if (threadIdx.x == 0) out[0] = sred[0];
}

extern "C" void kernel_launch(void* const* d_in, const int* in_sizes, int n_in,
                              void* d_out, int out_size) {
    const float* source  = (const float*)d_in[0];
    const float* target  = (const float*)d_in[1];
    const float* weights = (const float*)d_in[2];
    float* out = (float*)d_out;

    dim3 grid(CGROUPS, RTILES, B);
    tile_kernel<<<grid, 256>>>(source, target);

    finalize1_kernel<<<(B * N + B * M) / 256, 256>>>(weights);
    finalize2_kernel<<<1, 256>>>(out);
}

// round 15
// speedup vs baseline: 1.0879x; 1.0677x over previous
#include <cuda_runtime.h>
#include <math.h>

#define B 4
#define N 8192
#define M 8192
#define EPS 1e-8f
#define TSR 256   // source rows per CTA
#define TSC 128   // target cols per tile
#define NT  8     // col tiles swept per CTA
#define CGROUPS (M / (TSC * NT))   // 8 col groups
#define RTILES (N / TSR)           // 32

typedef unsigned long long u64;

__device__ float g_rowpart[B * CGROUPS * N];   // [b][colGroup][row]
__device__ float g_colpart[B * RTILES * M];    // [b][rowTile][col]
__device__ float g_bsum[256];

// ---------------- packed f32x2 helpers ----------------
__device__ __forceinline__ u64 pk2(float a, float b) {
    u64 r;
    asm("mov.b64 %0, {%1, %2};" : "=l"(r) : "f"(a), "f"(b));
    return r;
}
__device__ __forceinline__ u64 add2(u64 a, u64 b) {
    u64 r;
    asm("add.rn.f32x2 %0, %1, %2;" : "=l"(r) : "l"(a), "l"(b));
    return r;
}
__device__ __forceinline__ u64 fma2(u64 a, u64 b, u64 c) {
    u64 r;
    asm("fma.rn.f32x2 %0, %1, %2, %3;" : "=l"(r) : "l"(a), "l"(b), "l"(c));
    return r;
}
__device__ __forceinline__ float2 u2f(u64 v) {
    float2 f;
    asm("mov.b64 {%0, %1}, %2;" : "=f"(f.x), "=f"(f.y) : "l"(v));
    return f;
}

// ---------------- fused sweep kernel ----------------
// R10 structure: CTA = 256 rows x (8 tiles of 128 cols), source register-resident
// as vertical f32x2 pairs, conflict-free target LDS (col = c*16 + txi).
// NEW: min-block pipelined one 'a' behind the fma-block; col-min accumulators
// split into two chains to halve the serial FMNMX depth.
__global__ __launch_bounds__(256, 2) void tile_kernel(const float* __restrict__ source,
                                                      const float* __restrict__ target) {
    __shared__ __align__(16) float s_x[TSR], s_y[TSR], s_z[TSR], s_n[TSR];   // scalar source
    __shared__ __align__(16) u64 td_x[TSC], td_y[TSC], td_z[TSC], td_n[TSC]; // dup (-2t), (nt)
    __shared__ float red[TSR * 17];

    const int tid = threadIdx.x;
    const int b   = blockIdx.z;
    const int row0 = blockIdx.y * TSR;
    const int g    = blockIdx.x;
    const int colg0 = g * (TSC * NT);

    // Stage source (scalar): one row per thread
    {
        const float* sp = source + ((long)b * N + row0 + tid) * 3;
        float vx = sp[0], vy = sp[1], vz = sp[2];
        s_x[tid] = vx; s_y[tid] = vy; s_z[tid] = vz;
        s_n[tid] = vx * vx + vy * vy + vz * vz;
    }
    // Stage first target tile: duplicated pairs
    if (tid < TSC) {
        const float* tp = target + ((long)b * M + colg0 + tid) * 3;
        float vx = tp[0], vy = tp[1], vz = tp[2];
        td_x[tid] = pk2(-2.0f * vx, -2.0f * vx);
        td_y[tid] = pk2(-2.0f * vy, -2.0f * vy);
        td_z[tid] = pk2(-2.0f * vz, -2.0f * vz);
        float n = vx * vx + vy * vy + vz * vz;
        td_n[tid] = pk2(n, n);
    }
    __syncthreads();

    const int txi = tid & 15;
    const int tyi = tid >> 4;
    const int r0 = tyi * 16;  // this thread's 16 rows

    // Load source row-pairs into registers ONCE (LDS.64 of adjacent scalars)
    u64 px[8], py[8], pz[8], pn[8];
#pragma unroll
    for (int a = 0; a < 8; a++) {
        px[a] = *reinterpret_cast<const u64*>(&s_x[r0 + 2 * a]);
        py[a] = *reinterpret_cast<const u64*>(&s_y[r0 + 2 * a]);
        pz[a] = *reinterpret_cast<const u64*>(&s_z[r0 + 2 * a]);
        pn[a] = *reinterpret_cast<const u64*>(&s_n[r0 + 2 * a]);
    }

    const float BIGF = 3.4e38f;
    float rmin[16];
#pragma unroll
    for (int i = 0; i < 16; i++) rmin[i] = BIGF;

    float nx = 0.f, ny = 0.f, nz = 0.f;  // next-tile prefetch

    for (int ct = 0; ct < NT; ct++) {
        if (ct + 1 < NT && tid < TSC) {
            const float* tp = target + ((long)b * M + colg0 + (ct + 1) * TSC + tid) * 3;
            nx = tp[0]; ny = tp[1]; nz = tp[2];
        }

#pragma unroll
        for (int c = 0; c < 8; c++) {
            const int col = c * 16 + txi;   // unit stride across lanes: conflict-free
            u64 tx = td_x[col], ty = td_y[col], tz = td_z[col], tn = td_n[col];
            // Two independent chains per col-min half to shorten FMNMX depth.
            float c0a = BIGF, c0b = BIGF, c1a = BIGF, c1b = BIGF;

            // Software pipeline over 'a': compute q for a, min q from a-1.
            u64 qp = fma2(px[0], tx, add2(pn[0], tn));
            qp = fma2(py[0], ty, qp);
            qp = fma2(pz[0], tz, qp);
#pragma unroll
            for (int a = 1; a < 8; a++) {
                u64 qc = fma2(px[a], tx, add2(pn[a], tn));
                qc = fma2(py[a], ty, qc);
                qc = fma2(pz[a], tz, qc);
                // consume q from a-1 (operands are 8+ instructions old)
                float2 f = u2f(qp);
                rmin[2 * (a - 1)]     = fminf(rmin[2 * (a - 1)], f.x);
                rmin[2 * (a - 1) + 1] = fminf(rmin[2 * (a - 1) + 1], f.y);
                if (a & 1) { c0a = fminf(c0a, f.x); c1a = fminf(c1a, f.y); }
                else       { c0b = fminf(c0b, f.x); c1b = fminf(c1b, f.y); }
                qp = qc;
            }
            // drain a=7
            {
                float2 f = u2f(qp);
                rmin[14] = fminf(rmin[14], f.x);
                rmin[15] = fminf(rmin[15], f.y);
                c0b = fminf(c0b, f.x);
                c1b = fminf(c1b, f.y);
            }
            red[col * 17 + tyi] = fminf(fminf(c0a, c0b), fminf(c1a, c1b));
        }
        __syncthreads();
        // col-min reduction across tyi (16 values per col)
        if (tid < TSC) {
            float m = red[tid * 17];
#pragma unroll
            for (int k = 1; k < 16; k++) m = fminf(m, red[tid * 17 + k]);
            g_colpart[((long)b * RTILES + blockIdx.y) * M + colg0 + ct * TSC + tid] = m;
        }
        __syncthreads();

        // Commit prefetched target tile
        if (ct + 1 < NT) {
            if (tid < TSC) {
                td_x[tid] = pk2(-2.0f * nx, -2.0f * nx);
                td_y[tid] = pk2(-2.0f * ny, -2.0f * ny);
                td_z[tid] = pk2(-2.0f * nz, -2.0f * nz);
                float n = nx * nx + ny * ny + nz * nz;
                td_n[tid] = pk2(n, n);
            }
            __syncthreads();
        }
    }

    // ---- row-min reduction (across txi), once per CTA ----
#pragma unroll
    for (int i = 0; i < 16; i++) red[(r0 + i) * 17 + txi] = rmin[i];
    __syncthreads();
    {
        float m = red[tid * 17];
#pragma unroll
        for (int k = 1; k < 16; k++) m = fminf(m, red[tid * 17 + k]);
        g_rowpart[((long)b * CGROUPS + g) * N + row0 + tid] = m;
    }
}

// ---------------- finalize pass 1: reduce partials, block sums ----------------
__global__ void finalize1_kernel(const float* __restrict__ weights) {
    __shared__ float sred[256];
    int tid = blockIdx.x * blockDim.x + threadIdx.x;
    float v;
    if (tid < B * N) {
        int b = tid >> 13, row = tid & 8191;
        const float* p = &g_rowpart[((long)b * CGROUPS) * N + row];
        float m = p[0];
#pragma unroll 8
        for (int ct = 1; ct < CGROUPS; ct++) m = fminf(m, p[(long)ct * N]);
        v = sqrtf(m + EPS) * weights[tid] * (1.0f / (B * N));
    } else {
        int t = tid - B * N;
        int b = t >> 13, col = t & 8191;
        const float* p = &g_colpart[((long)b * RTILES) * M + col];
        float m = p[0];
#pragma unroll 8
        for (int rt = 1; rt < RTILES; rt++) m = fminf(m, p[(long)rt * M]);
        v = sqrtf(m + EPS) * (1.0f / (B * M));
    }
    sred[threadIdx.x] = v;
    __syncthreads();
    for (int s = 128; s > 0; s >>= 1) {
        if (threadIdx.x < s) sred[threadIdx.x] += sred[threadIdx.x + s];
        __syncthreads();
    }
    if (threadIdx.x == 0) g_bsum[blockIdx.x] = sred[0];
}

// ---------------- finalize pass 2: single block, plain store ----------------
__global__ void finalize2_kernel(float* __restrict__ out) {
    __shared__ float sred[256];
    sred[threadIdx.x] = g_bsum[threadIdx.x];
    __syncthreads();
    for (int s = 128; s > 0; s >>= 1) {
        if (threadIdx.x < s) sred[threadIdx.x] += sred[threadIdx.x + s];
        __syncthreads();
    }
    if (threadIdx.x == 0) out[0] = sred[0];
}

extern "C" void kernel_launch(void* const* d_in, const int* in_sizes, int n_in,
                              void* d_out, int out_size) {
    const float* source  = (const float*)d_in[0];
    const float* target  = (const float*)d_in[1];
    const float* weights = (const float*)d_in[2];
    float* out = (float*)d_out;

    dim3 grid(CGROUPS, RTILES, B);
    tile_kernel<<<grid, 256>>>(source, target);

    finalize1_kernel<<<(B * N + B * M) / 256, 256>>>(weights);
    finalize2_kernel<<<1, 256>>>(out);
}